// round 2
// baseline (speedup 1.0000x reference)
#include <cuda_runtime.h>
#include <math.h>

#define BSZ 16
#define CCH 512
#define NSP 1024
#define NGROUPS 32

// Scratch buffers (device globals -- no allocation allowed)
__device__ float g_h[(long)BSZ*CCH*NSP];
__device__ float g_q[(long)BSZ*CCH*NSP];
__device__ float g_k[(long)BSZ*CCH*NSP];
__device__ float g_v[(long)BSZ*CCH*NSP];
__device__ float g_attn[(long)BSZ*NSP*NSP];
__device__ float g_hv[(long)BSZ*CCH*NSP];

__device__ __forceinline__ float blockReduceSum(float v, float* sh) {
    int lane = threadIdx.x & 31, w = threadIdx.x >> 5;
    #pragma unroll
    for (int o = 16; o; o >>= 1) v += __shfl_down_sync(0xffffffffu, v, o);
    if (lane == 0) sh[w] = v;
    __syncthreads();
    if (w == 0) {
        float r = (lane < (int)(blockDim.x >> 5)) ? sh[lane] : 0.f;
        #pragma unroll
        for (int o = 16; o; o >>= 1) r += __shfl_down_sync(0xffffffffu, r, o);
        if (lane == 0) sh[0] = r;
    }
    __syncthreads();
    float r = sh[0];
    __syncthreads();
    return r;
}

__device__ __forceinline__ float blockReduceMax(float v, float* sh) {
    int lane = threadIdx.x & 31, w = threadIdx.x >> 5;
    #pragma unroll
    for (int o = 16; o; o >>= 1) v = fmaxf(v, __shfl_down_sync(0xffffffffu, v, o));
    if (lane == 0) sh[w] = v;
    __syncthreads();
    if (w == 0) {
        float r = (lane < (int)(blockDim.x >> 5)) ? sh[lane] : -1e30f;
        #pragma unroll
        for (int o = 16; o; o >>= 1) r = fmaxf(r, __shfl_down_sync(0xffffffffu, r, o));
        if (lane == 0) sh[0] = r;
    }
    __syncthreads();
    float r = sh[0];
    __syncthreads();
    return r;
}

// GroupNorm: one block per (batch, group). 16 channels x 1024 spatial = 16384 elems.
__global__ void gn_kernel(const float* __restrict__ x, const float* __restrict__ scale,
                          const float* __restrict__ bias) {
    __shared__ float sh[32];
    int b = blockIdx.x >> 5;
    int g = blockIdx.x & 31;
    const int CPG = CCH / NGROUPS;        // 16
    const int ELEMS = CPG * NSP;          // 16384
    const long base = ((long)b * CCH + (long)g * CPG) * NSP;
    const float* xp = x + base;
    float s = 0.f, ss = 0.f;
    for (int i = threadIdx.x; i < ELEMS; i += blockDim.x) {
        float v = xp[i];
        s += v; ss += v * v;
    }
    s  = blockReduceSum(s, sh);
    ss = blockReduceSum(ss, sh);
    const float inv_n = 1.f / (float)ELEMS;
    float mean = s * inv_n;
    float var  = ss * inv_n - mean * mean;
    float rinv = rsqrtf(var + 1e-5f);
    for (int i = threadIdx.x; i < ELEMS; i += blockDim.x) {
        int c = g * CPG + (i >> 10);   // i / NSP
        g_h[base + i] = (xp[i] - mean) * rinv * scale[c] + bias[c];
    }
}

// Row softmax over 1024 elems, in place. One block per row.
__global__ void softmax_kernel(float* __restrict__ attn) {
    __shared__ float sh[32];
    float* p = attn + (long)blockIdx.x * NSP;
    float m = -1e30f;
    for (int i = threadIdx.x; i < NSP; i += blockDim.x) m = fmaxf(m, p[i]);
    m = blockReduceMax(m, sh);
    float s = 0.f;
    for (int i = threadIdx.x; i < NSP; i += blockDim.x) {
        float e = __expf(p[i] - m);
        p[i] = e;
        s += e;
    }
    s = blockReduceSum(s, sh);
    float inv = 1.f / s;
    for (int i = threadIdx.x; i < NSP; i += blockDim.x) p[i] *= inv;
}

// Generic strided batched SGEMM: C[b][i][j] = alpha * sum_k A[i*sAm + k*sAk] * B[k*sBk + j*sBn]
//                                            (+ bias[i]) (+ residual[b][i][j])
// C and residual are row-major [M, Nn] per batch. 128x128 tile, BK=8, 8x8 per thread.
__global__ __launch_bounds__(256) void gemm_kernel(
    const float* __restrict__ A, const float* __restrict__ B,
    const float* __restrict__ bias, const float* __restrict__ Rres,
    float* __restrict__ Cc,
    int M, int Nn, int K,
    long sAm, long sAk, long sBk, long sBn,
    long batchA, long batchB, long batchC, long batchR,
    float alpha, int hasBias, int hasRes)
{
    __shared__ float As[8][128];
    __shared__ float Bs[8][128];
    int bz = blockIdx.z;
    A += (long)bz * batchA;
    B += (long)bz * batchB;
    Cc += (long)bz * batchC;
    const float* Rp = Rres ? (Rres + (long)bz * batchR) : nullptr;

    int tid = threadIdx.x;
    int tx = tid & 15, ty = tid >> 4;
    int rowBase = blockIdx.y * 128;
    int colBase = blockIdx.x * 128;

    float acc[8][8];
    #pragma unroll
    for (int i = 0; i < 8; i++)
        #pragma unroll
        for (int j = 0; j < 8; j++) acc[i][j] = 0.f;

    const bool aKfast = (sAk == 1);   // load k-contiguous if A's K stride is 1
    const bool bNslow = (sBn != 1);   // load k-contiguous if B's N stride isn't 1

    for (int k0 = 0; k0 < K; k0 += 8) {
        #pragma unroll
        for (int t = 0; t < 4; t++) {
            int idx = tid + t * 256;
            int m, kk;
            if (aKfast) { kk = idx & 7;  m = idx >> 3; }
            else        { m = idx & 127; kk = idx >> 7; }
            As[kk][m] = A[(long)(rowBase + m) * sAm + (long)(k0 + kk) * sAk];
            int n, kb;
            if (bNslow) { kb = idx & 7;  n = idx >> 3; }
            else        { n = idx & 127; kb = idx >> 7; }
            Bs[kb][n] = B[(long)(k0 + kb) * sBk + (long)(colBase + n) * sBn];
        }
        __syncthreads();
        #pragma unroll
        for (int kk = 0; kk < 8; kk++) {
            float aR[8], bR[8];
            #pragma unroll
            for (int i = 0; i < 8; i++) aR[i] = As[kk][ty * 8 + i];
            #pragma unroll
            for (int j = 0; j < 8; j++) bR[j] = Bs[kk][tx * 8 + j];
            #pragma unroll
            for (int i = 0; i < 8; i++)
                #pragma unroll
                for (int j = 0; j < 8; j++)
                    acc[i][j] = fmaf(aR[i], bR[j], acc[i][j]);
        }
        __syncthreads();
    }

    #pragma unroll
    for (int i = 0; i < 8; i++) {
        int row = rowBase + ty * 8 + i;
        float bv = hasBias ? bias[row] : 0.f;
        long rOff = (long)row * Nn + colBase + tx * 8;
        #pragma unroll
        for (int j = 0; j < 8; j++) {
            float v = acc[i][j] * alpha + bv;
            if (hasRes) v += Rp[rOff + j];
            Cc[rOff + j] = v;
        }
    }
}

extern "C" void kernel_launch(void* const* d_in, const int* in_sizes, int n_in,
                              void* d_out, int out_size) {
    const float* x  = (const float*)d_in[0];
    const float* gs = (const float*)d_in[1];
    const float* gb = (const float*)d_in[2];
    const float* wq = (const float*)d_in[3];
    const float* bq = (const float*)d_in[4];
    const float* wk = (const float*)d_in[5];
    const float* bk = (const float*)d_in[6];
    const float* wv = (const float*)d_in[7];
    const float* bv = (const float*)d_in[8];
    const float* wo = (const float*)d_in[9];
    const float* bo = (const float*)d_in[10];
    float* out = (float*)d_out;

    float *h, *q, *k, *v, *attn, *hv;
    cudaGetSymbolAddress((void**)&h,    g_h);
    cudaGetSymbolAddress((void**)&q,    g_q);
    cudaGetSymbolAddress((void**)&k,    g_k);
    cudaGetSymbolAddress((void**)&v,    g_v);
    cudaGetSymbolAddress((void**)&attn, g_attn);
    cudaGetSymbolAddress((void**)&hv,   g_hv);

    const long CN = (long)CCH * NSP;   // 524288
    const long NN = (long)NSP * NSP;   // 1048576
    const float scl = 1.0f / sqrtf((float)CCH);

    // 1) GroupNorm -> g_h
    gn_kernel<<<BSZ * NGROUPS, 256>>>(x, gs, gb);

    // 2) Q, K, V projections: [512x512] x [512x1024] per batch
    dim3 gProj(NSP / 128, CCH / 128, BSZ);
    gemm_kernel<<<gProj, 256>>>(wq, h, bq, nullptr, q, CCH, NSP, CCH,
                                CCH, 1, NSP, 1, 0, CN, CN, 0, 1.f, 1, 0);
    gemm_kernel<<<gProj, 256>>>(wk, h, bk, nullptr, k, CCH, NSP, CCH,
                                CCH, 1, NSP, 1, 0, CN, CN, 0, 1.f, 1, 0);
    gemm_kernel<<<gProj, 256>>>(wv, h, bv, nullptr, v, CCH, NSP, CCH,
                                CCH, 1, NSP, 1, 0, CN, CN, 0, 1.f, 1, 0);

    // 3) Scores: S[n,m] = scale * sum_c q[c,n] k[c,m]   (M=N=1024, K=512)
    dim3 gScore(NSP / 128, NSP / 128, BSZ);
    gemm_kernel<<<gScore, 256>>>(q, k, nullptr, nullptr, attn, NSP, NSP, CCH,
                                 1, NSP, NSP, 1, CN, CN, NN, 0, scl, 0, 0);

    // 4) Row softmax over m, in place
    softmax_kernel<<<BSZ * NSP, 256>>>(attn);

    // 5) hv[c,n] = sum_m v[c,m] * w[n,m]   (M=512, N=1024, K=1024)
    gemm_kernel<<<gProj, 256>>>(v, attn, nullptr, nullptr, hv, CCH, NSP, NSP,
                                NSP, 1, 1, NSP, CN, NN, CN, 0, 1.f, 0, 0);

    // 6) Output projection + bias + residual
    gemm_kernel<<<gProj, 256>>>(wo, hv, bo, x, out, CCH, NSP, CCH,
                                CCH, 1, NSP, 1, 0, CN, CN, CN, 1.f, 1, 1);
}

// round 4
// speedup vs baseline: 2.8574x; 2.8574x over previous
#include <cuda_runtime.h>
#include <cuda_bf16.h>
#include <mma.h>
#include <math.h>

using namespace nvcuda;

#define BSZ 16
#define CCH 512
#define NSP 1024
#define NGROUPS 32

#define BM 128
#define BN 128
#define BK 32
#define PADA 8   // As row pad (elems)
#define PADB 8   // Bs row pad

// Scratch buffers (device globals -- no allocation allowed)
__device__ float g_h[(long)BSZ*CCH*NSP];
__device__ float g_q[(long)BSZ*CCH*NSP];
__device__ float g_k[(long)BSZ*CCH*NSP];
__device__ float g_v[(long)BSZ*CCH*NSP];
__device__ float g_attn[(long)BSZ*NSP*NSP];
__device__ float g_hv[(long)BSZ*CCH*NSP];

__device__ __forceinline__ float blockReduceSum(float v, float* sh) {
    int lane = threadIdx.x & 31, w = threadIdx.x >> 5;
    #pragma unroll
    for (int o = 16; o; o >>= 1) v += __shfl_down_sync(0xffffffffu, v, o);
    if (lane == 0) sh[w] = v;
    __syncthreads();
    if (w == 0) {
        float r = (lane < (int)(blockDim.x >> 5)) ? sh[lane] : 0.f;
        #pragma unroll
        for (int o = 16; o; o >>= 1) r += __shfl_down_sync(0xffffffffu, r, o);
        if (lane == 0) sh[0] = r;
    }
    __syncthreads();
    float r = sh[0];
    __syncthreads();
    return r;
}

__device__ __forceinline__ float blockReduceMax(float v, float* sh) {
    int lane = threadIdx.x & 31, w = threadIdx.x >> 5;
    #pragma unroll
    for (int o = 16; o; o >>= 1) v = fmaxf(v, __shfl_down_sync(0xffffffffu, v, o));
    if (lane == 0) sh[w] = v;
    __syncthreads();
    if (w == 0) {
        float r = (lane < (int)(blockDim.x >> 5)) ? sh[lane] : -1e30f;
        #pragma unroll
        for (int o = 16; o; o >>= 1) r = fmaxf(r, __shfl_down_sync(0xffffffffu, r, o));
        if (lane == 0) sh[0] = r;
    }
    __syncthreads();
    float r = sh[0];
    __syncthreads();
    return r;
}

// GroupNorm: one block per (batch, group). 16 channels x 1024 spatial = 16384 elems.
__global__ void gn_kernel(const float* __restrict__ x, const float* __restrict__ scale,
                          const float* __restrict__ bias) {
    __shared__ float sh[32];
    int b = blockIdx.x >> 5;
    int g = blockIdx.x & 31;
    const int CPG = CCH / NGROUPS;        // 16
    const int ELEMS = CPG * NSP;          // 16384
    const long base = ((long)b * CCH + (long)g * CPG) * NSP;
    const float* xp = x + base;
    float s = 0.f, ss = 0.f;
    for (int i = threadIdx.x; i < ELEMS; i += blockDim.x) {
        float v = xp[i];
        s += v; ss += v * v;
    }
    s  = blockReduceSum(s, sh);
    ss = blockReduceSum(ss, sh);
    const float inv_n = 1.f / (float)ELEMS;
    float mean = s * inv_n;
    float var  = ss * inv_n - mean * mean;
    float rinv = rsqrtf(var + 1e-5f);
    for (int i = threadIdx.x; i < ELEMS; i += blockDim.x) {
        int c = g * CPG + (i >> 10);   // i / NSP
        g_h[base + i] = (xp[i] - mean) * rinv * scale[c] + bias[c];
    }
}

// Single-pass row softmax: row cached in registers (4 floats / thread).
__global__ __launch_bounds__(256) void softmax_kernel(float* __restrict__ attn) {
    __shared__ float sh[32];
    float4* p = (float4*)(attn + (long)blockIdx.x * NSP);
    float4 v = p[threadIdx.x];
    float m = fmaxf(fmaxf(v.x, v.y), fmaxf(v.z, v.w));
    m = blockReduceMax(m, sh);
    v.x = __expf(v.x - m); v.y = __expf(v.y - m);
    v.z = __expf(v.z - m); v.w = __expf(v.w - m);
    float s = v.x + v.y + v.z + v.w;
    s = blockReduceSum(s, sh);
    float inv = 1.f / s;
    v.x *= inv; v.y *= inv; v.z *= inv; v.w *= inv;
    p[threadIdx.x] = v;
}

// Generic strided batched GEMM on tensor cores (bf16 in / fp32 acc).
// C[b][i][j] = alpha * sum_k A[i*sAm + k*sAk] * B[k*sBk + j*sBn]
// fp32 global operands are converted to bf16 when staged into smem.
__global__ __launch_bounds__(256) void gemm_bf16(
    const float* __restrict__ A, const float* __restrict__ B,
    float* __restrict__ Cc,
    int M, int Nn, int K,
    long sAm, long sAk, long sBk, long sBn,
    long batchA, long batchB, long batchC,
    float alpha)
{
    __shared__ __align__(32) __nv_bfloat16 As[BM][BK + PADA];
    __shared__ __align__(32) __nv_bfloat16 Bs[BK][BN + PADB];

    int bz = blockIdx.z;
    A += (long)bz * batchA;
    B += (long)bz * batchB;
    Cc += (long)bz * batchC;

    const int tid = threadIdx.x;
    const int warp = tid >> 5;
    const int wn = warp & 3;   // 4 warps along N -> 32 cols each
    const int wm = warp >> 2;  // 2 warps along M -> 64 rows each
    const int rowBase = blockIdx.y * BM;
    const int colBase = blockIdx.x * BN;

    wmma::fragment<wmma::accumulator, 16, 16, 16, float> acc[4][2];
    #pragma unroll
    for (int i = 0; i < 4; i++)
        #pragma unroll
        for (int j = 0; j < 2; j++) wmma::fill_fragment(acc[i][j], 0.f);

    const bool aKfast = (sAk == 1);
    const bool bNfast = (sBn == 1);

    for (int k0 = 0; k0 < K; k0 += BK) {
        // Stage A tile (BM x BK = 4096 elems, 16 per thread)
        #pragma unroll
        for (int t = 0; t < 16; t++) {
            int idx = tid + t * 256;
            int m, kk;
            if (aKfast) { kk = idx & (BK - 1); m = idx >> 5; }
            else        { m = idx & (BM - 1); kk = idx >> 7; }
            As[m][kk] = __float2bfloat16(
                A[(long)(rowBase + m) * sAm + (long)(k0 + kk) * sAk]);
        }
        // Stage B tile (BK x BN = 4096 elems)
        #pragma unroll
        for (int t = 0; t < 16; t++) {
            int idx = tid + t * 256;
            int n, kk;
            if (bNfast) { n = idx & (BN - 1); kk = idx >> 7; }
            else        { kk = idx & (BK - 1); n = idx >> 5; }
            Bs[kk][n] = __float2bfloat16(
                B[(long)(k0 + kk) * sBk + (long)(colBase + n) * sBn]);
        }
        __syncthreads();

        #pragma unroll
        for (int ks = 0; ks < BK; ks += 16) {
            wmma::fragment<wmma::matrix_a, 16, 16, 16, __nv_bfloat16, wmma::row_major> af[4];
            wmma::fragment<wmma::matrix_b, 16, 16, 16, __nv_bfloat16, wmma::row_major> bf[2];
            #pragma unroll
            for (int i = 0; i < 4; i++)
                wmma::load_matrix_sync(af[i], &As[wm * 64 + i * 16][ks], BK + PADA);
            #pragma unroll
            for (int j = 0; j < 2; j++)
                wmma::load_matrix_sync(bf[j], &Bs[ks][wn * 32 + j * 16], BN + PADB);
            #pragma unroll
            for (int i = 0; i < 4; i++)
                #pragma unroll
                for (int j = 0; j < 2; j++)
                    wmma::mma_sync(acc[i][j], af[i], bf[j], acc[i][j]);
        }
        __syncthreads();
    }

    #pragma unroll
    for (int i = 0; i < 4; i++) {
        #pragma unroll
        for (int j = 0; j < 2; j++) {
            #pragma unroll
            for (int t = 0; t < (int)acc[i][j].num_elements; t++)
                acc[i][j].x[t] *= alpha;
            float* cp = Cc + (long)(rowBase + wm * 64 + i * 16) * Nn
                           + colBase + wn * 32 + j * 16;
            wmma::store_matrix_sync(cp, acc[i][j], Nn, wmma::mem_row_major);
        }
    }
}

// p[b][c][n] += bias[c], vectorized float4 over BSZ*CCH*NSP elems
__global__ __launch_bounds__(256) void addbias_kernel(float* __restrict__ p,
                                                      const float* __restrict__ bias) {
    long i = (long)blockIdx.x * blockDim.x + threadIdx.x;  // float4 index
    float b = bias[(i >> 8) & (CCH - 1)];                  // (4i / 1024) % 512
    float4 v = ((float4*)p)[i];
    v.x += b; v.y += b; v.z += b; v.w += b;
    ((float4*)p)[i] = v;
}

// out += bo[c] + x   (final residual + bias)
__global__ __launch_bounds__(256) void final_kernel(float* __restrict__ out,
                                                    const float* __restrict__ x,
                                                    const float* __restrict__ bo) {
    long i = (long)blockIdx.x * blockDim.x + threadIdx.x;
    float b = bo[(i >> 8) & (CCH - 1)];
    float4 v = ((float4*)out)[i];
    float4 xx = ((const float4*)x)[i];
    v.x += b + xx.x; v.y += b + xx.y; v.z += b + xx.z; v.w += b + xx.w;
    ((float4*)out)[i] = v;
}

extern "C" void kernel_launch(void* const* d_in, const int* in_sizes, int n_in,
                              void* d_out, int out_size) {
    const float* x  = (const float*)d_in[0];
    const float* gs = (const float*)d_in[1];
    const float* gb = (const float*)d_in[2];
    const float* wq = (const float*)d_in[3];
    const float* bq = (const float*)d_in[4];
    const float* wk = (const float*)d_in[5];
    const float* bk = (const float*)d_in[6];
    const float* wv = (const float*)d_in[7];
    const float* bv = (const float*)d_in[8];
    const float* wo = (const float*)d_in[9];
    const float* bo = (const float*)d_in[10];
    float* out = (float*)d_out;

    float *h, *q, *k, *v, *attn, *hv;
    cudaGetSymbolAddress((void**)&h,    g_h);
    cudaGetSymbolAddress((void**)&q,    g_q);
    cudaGetSymbolAddress((void**)&k,    g_k);
    cudaGetSymbolAddress((void**)&v,    g_v);
    cudaGetSymbolAddress((void**)&attn, g_attn);
    cudaGetSymbolAddress((void**)&hv,   g_hv);

    const long CN = (long)CCH * NSP;   // 524288
    const long NN = (long)NSP * NSP;   // 1048576
    const float scl = 1.0f / sqrtf((float)CCH);
    const int nVec4 = (int)((long)BSZ * CN / 4 / 256);  // blocks for elementwise

    // 1) GroupNorm -> g_h (fp32)
    gn_kernel<<<BSZ * NGROUPS, 256>>>(x, gs, gb);

    // 2) Q, K, V projections: [512x512] x [512x1024] per batch
    dim3 gProj(NSP / BN, CCH / BM, BSZ);
    gemm_bf16<<<gProj, 256>>>(wq, h, q, CCH, NSP, CCH,
                              CCH, 1, NSP, 1, 0, CN, CN, 1.f);
    gemm_bf16<<<gProj, 256>>>(wk, h, k, CCH, NSP, CCH,
                              CCH, 1, NSP, 1, 0, CN, CN, 1.f);
    gemm_bf16<<<gProj, 256>>>(wv, h, v, CCH, NSP, CCH,
                              CCH, 1, NSP, 1, 0, CN, CN, 1.f);
    addbias_kernel<<<nVec4, 256>>>(q, bq);
    addbias_kernel<<<nVec4, 256>>>(k, bk);
    addbias_kernel<<<nVec4, 256>>>(v, bv);

    // 3) Scores: S[n,m] = scale * sum_c q[c,n] k[c,m]   (M=N=1024, K=512)
    dim3 gScore(NSP / BN, NSP / BM, BSZ);
    gemm_bf16<<<gScore, 256>>>(q, k, attn, NSP, NSP, CCH,
                               1, NSP, NSP, 1, CN, CN, NN, scl);

    // 4) Row softmax over m, in place (single pass)
    softmax_kernel<<<BSZ * NSP, 256>>>(attn);

    // 5) hv[c,n] = sum_m v[c,m] * w[n,m]   (M=512, N=1024, K=1024)
    gemm_bf16<<<gProj, 256>>>(v, attn, hv, CCH, NSP, NSP,
                              NSP, 1, 1, NSP, CN, NN, CN, 1.f);

    // 6) Output projection, then bias + residual epilogue
    gemm_bf16<<<gProj, 256>>>(wo, hv, out, CCH, NSP, CCH,
                              CCH, 1, NSP, 1, 0, CN, CN, 1.f);
    final_kernel<<<nVec4, 256>>>(out, x, bo);
}

// round 5
// speedup vs baseline: 5.5983x; 1.9592x over previous
#include <cuda_runtime.h>
#include <cuda_bf16.h>
#include <mma.h>
#include <math.h>

using namespace nvcuda;
typedef __nv_bfloat16 bf16;

#define BSZ 16
#define CCH 512
#define NSP 1024
#define NGROUPS 32

#define BM 128
#define BN 128
#define BK 32
#define PAD 8

// Scratch (device globals -- no allocation allowed). All bf16.
__device__ __align__(16) bf16 g_h[(long)BSZ*CCH*NSP];
__device__ __align__(16) bf16 g_q[(long)BSZ*CCH*NSP];
__device__ __align__(16) bf16 g_k[(long)BSZ*CCH*NSP];
__device__ __align__(16) bf16 g_v[(long)BSZ*CCH*NSP];
__device__ __align__(16) bf16 g_attn[(long)BSZ*NSP*NSP];
__device__ __align__(16) bf16 g_hv[(long)BSZ*CCH*NSP];
__device__ __align__(16) bf16 g_w16[4L*CCH*CCH];

template<bool C, class T, class F> struct Sel { using type = T; };
template<class T, class F> struct Sel<false, T, F> { using type = F; };

__device__ __forceinline__ unsigned pk(float a, float b) {
    __nv_bfloat162 t = __floats2bfloat162_rn(a, b);
    return *(unsigned*)&t;
}

__device__ __forceinline__ void cp16(void* s, const void* g) {
    unsigned sa = (unsigned)__cvta_generic_to_shared(s);
    asm volatile("cp.async.cg.shared.global [%0], [%1], 16;" :: "r"(sa), "l"(g));
}
__device__ __forceinline__ void cp_commit() { asm volatile("cp.async.commit_group;"); }
__device__ __forceinline__ void cp_wait1() { asm volatile("cp.async.wait_group 1;"); }
__device__ __forceinline__ void cp_wait0() { asm volatile("cp.async.wait_group 0;"); }

__device__ __forceinline__ float blockReduceSum(float v, float* sh) {
    int lane = threadIdx.x & 31, w = threadIdx.x >> 5;
    #pragma unroll
    for (int o = 16; o; o >>= 1) v += __shfl_down_sync(0xffffffffu, v, o);
    if (lane == 0) sh[w] = v;
    __syncthreads();
    if (w == 0) {
        float r = (lane < (int)(blockDim.x >> 5)) ? sh[lane] : 0.f;
        #pragma unroll
        for (int o = 16; o; o >>= 1) r += __shfl_down_sync(0xffffffffu, r, o);
        if (lane == 0) sh[0] = r;
    }
    __syncthreads();
    float r = sh[0];
    __syncthreads();
    return r;
}

__device__ __forceinline__ float blockReduceMax(float v, float* sh) {
    int lane = threadIdx.x & 31, w = threadIdx.x >> 5;
    #pragma unroll
    for (int o = 16; o; o >>= 1) v = fmaxf(v, __shfl_down_sync(0xffffffffu, v, o));
    if (lane == 0) sh[w] = v;
    __syncthreads();
    if (w == 0) {
        float r = (lane < (int)(blockDim.x >> 5)) ? sh[lane] : -1e30f;
        #pragma unroll
        for (int o = 16; o; o >>= 1) r = fmaxf(r, __shfl_down_sync(0xffffffffu, r, o));
        if (lane == 0) sh[0] = r;
    }
    __syncthreads();
    float r = sh[0];
    __syncthreads();
    return r;
}

// GroupNorm: one block per (batch, group); fp32 in, bf16 out.
__global__ __launch_bounds__(256) void gn_kernel(const float* __restrict__ x,
                                                 const float* __restrict__ scale,
                                                 const float* __restrict__ bias) {
    __shared__ float sh[32];
    int b = blockIdx.x >> 5;
    int g = blockIdx.x & 31;
    const int VE = 16 * NSP / 4;   // 4096 float4
    const long base = ((long)b * CCH + (long)g * 16) * NSP;
    const float4* xp = (const float4*)(x + base);
    float s = 0.f, ss = 0.f;
    for (int i = threadIdx.x; i < VE; i += 256) {
        float4 t = xp[i];
        s  += t.x + t.y + t.z + t.w;
        ss += t.x * t.x + t.y * t.y + t.z * t.z + t.w * t.w;
    }
    s  = blockReduceSum(s, sh);
    ss = blockReduceSum(ss, sh);
    float mean = s * (1.f / 16384.f);
    float var  = ss * (1.f / 16384.f) - mean * mean;
    float rinv = rsqrtf(var + 1e-5f);
    uint2* hp = (uint2*)(g_h + base);
    for (int i = threadIdx.x; i < VE; i += 256) {
        int c = g * 16 + (i >> 8);
        float sc = scale[c] * rinv;
        float bi = bias[c] - mean * sc;
        float4 t = xp[i];
        uint2 o;
        o.x = pk(t.x * sc + bi, t.y * sc + bi);
        o.y = pk(t.z * sc + bi, t.w * sc + bi);
        hp[i] = o;
    }
}

// Convert the four 512x512 fp32 weights to bf16 (g_w16).
__global__ __launch_bounds__(256) void convw_kernel(const float* __restrict__ wq,
                                                    const float* __restrict__ wk,
                                                    const float* __restrict__ wv,
                                                    const float* __restrict__ wo) {
    const float* s = blockIdx.y == 0 ? wq : blockIdx.y == 1 ? wk : blockIdx.y == 2 ? wv : wo;
    bf16* d = g_w16 + (long)blockIdx.y * CCH * CCH;
    int iv = blockIdx.x * 256 + threadIdx.x;      // float4 index, 65536 total
    float4 v = ((const float4*)s)[iv];
    uint2 o;
    o.x = pk(v.x, v.y);
    o.y = pk(v.z, v.w);
    ((uint2*)d)[iv] = o;
}

// Row softmax over 1024 bf16, in place, single pass (row in registers).
__global__ __launch_bounds__(256) void softmax_kernel(bf16* __restrict__ attn) {
    __shared__ float sh[32];
    uint2* p = (uint2*)(attn + (long)blockIdx.x * NSP);
    uint2 raw = p[threadIdx.x];
    __nv_bfloat162 h0 = *(__nv_bfloat162*)&raw.x;
    __nv_bfloat162 h1 = *(__nv_bfloat162*)&raw.y;
    float a = __low2float(h0), b = __high2float(h0);
    float c = __low2float(h1), d = __high2float(h1);
    float m = fmaxf(fmaxf(a, b), fmaxf(c, d));
    m = blockReduceMax(m, sh);
    a = __expf(a - m); b = __expf(b - m); c = __expf(c - m); d = __expf(d - m);
    float s = a + b + c + d;
    s = blockReduceSum(s, sh);
    float inv = 1.f / s;
    raw.x = pk(a * inv, b * inv);
    raw.y = pk(c * inv, d * inv);
    p[threadIdx.x] = raw;
}

// Tensor-core batched GEMM, bf16 in / fp32 acc, cp.async double-buffered.
// C[b][i][j] = alpha * sum_k A[i*sAm + k*sAk] * B[k*sBk + j*sBn] (+bias[i]) (+res)
// AMODE 0: sAk==1 (k-fast)   AMODE 1: sAm==1 (m-fast)
// BMODE 0: sBn==1 (n-fast)   BMODE 1: sBk==1 (k-fast)
template<int AMODE, int BMODE, bool HASB, bool HASR, bool F32O>
__global__ void __launch_bounds__(256, 2) gemm_tc(
    const bf16* __restrict__ A, const bf16* __restrict__ B,
    const float* __restrict__ bias, const float* __restrict__ res,
    void* __restrict__ Cv, int Nn, int K,
    long sAm, long sAk, long sBk, long sBn,
    long batchA, long batchB, long batchC, float alpha)
{
    constexpr int AS_STR = (AMODE == 0) ? BK + PAD : BM + PAD;
    constexpr int A_TILE = (AMODE == 0) ? BM * AS_STR : BK * AS_STR;
    constexpr int BS_STR = (BMODE == 0) ? BN + PAD : BK + PAD;
    constexpr int B_TILE = (BMODE == 0) ? BK * BS_STR : BN * BS_STR;
    using AL = typename Sel<AMODE == 0, wmma::row_major, wmma::col_major>::type;
    using BL = typename Sel<BMODE == 0, wmma::row_major, wmma::col_major>::type;

    __shared__ __align__(16) bf16 sm[2 * A_TILE + 2 * B_TILE];
    bf16* As = sm;
    bf16* Bs = sm + 2 * A_TILE;

    const int bz = blockIdx.z;
    A += (long)bz * batchA;
    B += (long)bz * batchB;
    const int tid = threadIdx.x;
    const int warp = tid >> 5, lane = tid & 31;
    const int wn = warp & 1, wm = warp >> 1;     // warp tile 32(M) x 64(N)
    const int rowBase = blockIdx.y * BM;
    const int colBase = blockIdx.x * BN;

    wmma::fragment<wmma::accumulator, 16, 16, 16, float> acc[2][4];
    #pragma unroll
    for (int i = 0; i < 2; i++)
        #pragma unroll
        for (int j = 0; j < 4; j++) wmma::fill_fragment(acc[i][j], 0.f);

    auto stage = [&](int kt, int buf) {
        int k0 = kt * BK;
        #pragma unroll
        for (int t = 0; t < 2; t++) {
            int v = tid + t * 256;
            const bf16* ga; bf16* sa;
            if (AMODE == 0) {
                int m = v >> 2, kv = (v & 3) * 8;
                ga = A + (long)(rowBase + m) * sAm + (k0 + kv);
                sa = As + buf * A_TILE + m * AS_STR + kv;
            } else {
                int kk = v >> 4, mv = (v & 15) * 8;
                ga = A + (rowBase + mv) + (long)(k0 + kk) * sAk;
                sa = As + buf * A_TILE + kk * AS_STR + mv;
            }
            cp16(sa, ga);
        }
        #pragma unroll
        for (int t = 0; t < 2; t++) {
            int v = tid + t * 256;
            const bf16* gb; bf16* sb;
            if (BMODE == 0) {
                int kk = v >> 4, nv = (v & 15) * 8;
                gb = B + (long)(k0 + kk) * sBk + (colBase + nv);
                sb = Bs + buf * B_TILE + kk * BS_STR + nv;
            } else {
                int n = v >> 2, kv = (v & 3) * 8;
                gb = B + (long)(colBase + n) * sBn + (k0 + kv);
                sb = Bs + buf * B_TILE + n * BS_STR + kv;
            }
            cp16(sb, gb);
        }
        cp_commit();
    };

    const int KT = K >> 5;
    stage(0, 0);
    for (int kt = 0; kt < KT; kt++) {
        int buf = kt & 1;
        if (kt + 1 < KT) { stage(kt + 1, buf ^ 1); cp_wait1(); }
        else cp_wait0();
        __syncthreads();
        #pragma unroll
        for (int ks = 0; ks < BK; ks += 16) {
            wmma::fragment<wmma::matrix_a, 16, 16, 16, bf16, AL> af[2];
            wmma::fragment<wmma::matrix_b, 16, 16, 16, bf16, BL> bfm[4];
            #pragma unroll
            for (int i = 0; i < 2; i++) {
                const bf16* ap = (AMODE == 0)
                    ? As + buf * A_TILE + (wm * 32 + i * 16) * AS_STR + ks
                    : As + buf * A_TILE + ks * AS_STR + (wm * 32 + i * 16);
                wmma::load_matrix_sync(af[i], ap, AS_STR);
            }
            #pragma unroll
            for (int j = 0; j < 4; j++) {
                const bf16* bp = (BMODE == 0)
                    ? Bs + buf * B_TILE + ks * BS_STR + (wn * 64 + j * 16)
                    : Bs + buf * B_TILE + (wn * 64 + j * 16) * BS_STR + ks;
                wmma::load_matrix_sync(bfm[j], bp, BS_STR);
            }
            #pragma unroll
            for (int i = 0; i < 2; i++)
                #pragma unroll
                for (int j = 0; j < 4; j++)
                    wmma::mma_sync(acc[i][j], af[i], bfm[j], acc[i][j]);
        }
        __syncthreads();
    }

    // Epilogue: per-warp smem bounce (aliases tile smem), fp32->bf16 16B stores.
    float* cw = (float*)sm + warp * (16 * 20);
    float* Cf = (float*)Cv;
    bf16*  Cb = (bf16*)Cv;
    const long cbatch = (long)bz * batchC;
    const int r  = lane >> 1;
    const int cb = (lane & 1) * 8;
    #pragma unroll
    for (int i = 0; i < 2; i++) {
        #pragma unroll
        for (int j = 0; j < 4; j++) {
            #pragma unroll
            for (int t = 0; t < (int)acc[i][j].num_elements; t++)
                acc[i][j].x[t] *= alpha;
            wmma::store_matrix_sync(cw, acc[i][j], 20, wmma::mem_row_major);
            __syncwarp();
            float4 v0 = *(float4*)(cw + r * 20 + cb);
            float4 v1 = *(float4*)(cw + r * 20 + cb + 4);
            __syncwarp();
            int row = rowBase + wm * 32 + i * 16 + r;
            long coff = cbatch + (long)row * Nn + colBase + wn * 64 + j * 16 + cb;
            float ba = HASB ? bias[row] : 0.f;
            if (HASR) {
                const float4* rp = (const float4*)(res + coff);
                float4 r0 = rp[0], r1 = rp[1];
                v0.x += r0.x; v0.y += r0.y; v0.z += r0.z; v0.w += r0.w;
                v1.x += r1.x; v1.y += r1.y; v1.z += r1.z; v1.w += r1.w;
            }
            v0.x += ba; v0.y += ba; v0.z += ba; v0.w += ba;
            v1.x += ba; v1.y += ba; v1.z += ba; v1.w += ba;
            if (F32O) {
                *(float4*)(Cf + coff) = v0;
                *(float4*)(Cf + coff + 4) = v1;
            } else {
                uint4 u;
                u.x = pk(v0.x, v0.y); u.y = pk(v0.z, v0.w);
                u.z = pk(v1.x, v1.y); u.w = pk(v1.z, v1.w);
                *(uint4*)(Cb + coff) = u;
            }
        }
    }
}

extern "C" void kernel_launch(void* const* d_in, const int* in_sizes, int n_in,
                              void* d_out, int out_size) {
    const float* x  = (const float*)d_in[0];
    const float* gs = (const float*)d_in[1];
    const float* gb = (const float*)d_in[2];
    const float* wq = (const float*)d_in[3];
    const float* bq = (const float*)d_in[4];
    const float* wk = (const float*)d_in[5];
    const float* bk = (const float*)d_in[6];
    const float* wv = (const float*)d_in[7];
    const float* bv = (const float*)d_in[8];
    const float* wo = (const float*)d_in[9];
    const float* bo = (const float*)d_in[10];
    float* out = (float*)d_out;

    bf16 *h, *q, *k, *v, *attn, *hv, *w16;
    cudaGetSymbolAddress((void**)&h,    g_h);
    cudaGetSymbolAddress((void**)&q,    g_q);
    cudaGetSymbolAddress((void**)&k,    g_k);
    cudaGetSymbolAddress((void**)&v,    g_v);
    cudaGetSymbolAddress((void**)&attn, g_attn);
    cudaGetSymbolAddress((void**)&hv,   g_hv);
    cudaGetSymbolAddress((void**)&w16,  g_w16);

    const long CN = (long)CCH * NSP;   // 524288
    const long NN = (long)NSP * NSP;   // 1048576
    const long WW = (long)CCH * CCH;   // 262144
    const float scl = 1.0f / sqrtf((float)CCH);

    // 1) GroupNorm -> h (bf16); weights -> bf16
    gn_kernel<<<BSZ * NGROUPS, 256>>>(x, gs, gb);
    convw_kernel<<<dim3(WW / 4 / 256, 4), 256>>>(wq, wk, wv, wo);

    // 2) Q, K, V projections: w[512,512] @ h[512,1024] per batch (+bias)
    dim3 gProj(NSP / BN, CCH / BM, BSZ);
    gemm_tc<0,0,true,false,false><<<gProj, 256>>>(w16 + 0*WW, h, bq, nullptr, q,
        NSP, CCH, CCH, 1, NSP, 1, 0, CN, CN, 1.f);
    gemm_tc<0,0,true,false,false><<<gProj, 256>>>(w16 + 1*WW, h, bk, nullptr, k,
        NSP, CCH, CCH, 1, NSP, 1, 0, CN, CN, 1.f);
    gemm_tc<0,0,true,false,false><<<gProj, 256>>>(w16 + 2*WW, h, bv, nullptr, v,
        NSP, CCH, CCH, 1, NSP, 1, 0, CN, CN, 1.f);

    // 3) Scores: S[n,m] = scl * sum_c q[c,n] k[c,m]  (M=N=1024, K=512)
    dim3 gScore(NSP / BN, NSP / BM, BSZ);
    gemm_tc<1,0,false,false,false><<<gScore, 256>>>(q, k, nullptr, nullptr, attn,
        NSP, CCH, 1, NSP, NSP, 1, CN, CN, NN, scl);

    // 4) Row softmax (bf16 in/out)
    softmax_kernel<<<BSZ * NSP, 256>>>(attn);

    // 5) hv[c,n] = sum_m v[c,m] * attn[n,m]  (M=512, N=1024, K=1024)
    gemm_tc<0,1,false,false,false><<<gProj, 256>>>(v, attn, nullptr, nullptr, hv,
        NSP, NSP, NSP, 1, 1, NSP, CN, NN, CN, 1.f);

    // 6) out = wo @ hv + bo + x  (fp32 output)
    gemm_tc<0,0,true,true,true><<<gProj, 256>>>(w16 + 3*WW, hv, bo, x, out,
        NSP, CCH, CCH, 1, NSP, 1, 0, CN, CN, 1.f);
}

// round 9
// speedup vs baseline: 5.6794x; 1.0145x over previous
#include <cuda_runtime.h>
#include <cuda_bf16.h>
#include <mma.h>
#include <math.h>

using namespace nvcuda;
typedef __nv_bfloat16 bf16;

#define BSZ 16
#define CCH 512
#define NSP 1024
#define NGROUPS 32

#define BM 128
#define BN 256
#define BK 32
#define PAD 8

// Scratch (device globals -- no allocation allowed). All bf16.
__device__ __align__(16) bf16 g_h[(long)BSZ*CCH*NSP];
__device__ __align__(16) bf16 g_q[(long)BSZ*CCH*NSP];
__device__ __align__(16) bf16 g_k[(long)BSZ*CCH*NSP];
__device__ __align__(16) bf16 g_v[(long)BSZ*CCH*NSP];
__device__ __align__(16) bf16 g_attn[(long)BSZ*NSP*NSP];
__device__ __align__(16) bf16 g_hv[(long)BSZ*CCH*NSP];
__device__ __align__(16) bf16 g_w16[4L*CCH*CCH];

template<bool C, class T, class F> struct Sel { using type = T; };
template<class T, class F> struct Sel<false, T, F> { using type = F; };

__device__ __forceinline__ unsigned pk(float a, float b) {
    __nv_bfloat162 t = __floats2bfloat162_rn(a, b);
    return *(unsigned*)&t;
}

__device__ __forceinline__ void cp16(void* s, const void* g) {
    unsigned sa = (unsigned)__cvta_generic_to_shared(s);
    asm volatile("cp.async.cg.shared.global [%0], [%1], 16;" :: "r"(sa), "l"(g));
}
__device__ __forceinline__ void cp_commit() { asm volatile("cp.async.commit_group;"); }
__device__ __forceinline__ void cp_wait1() { asm volatile("cp.async.wait_group 1;"); }
__device__ __forceinline__ void cp_wait0() { asm volatile("cp.async.wait_group 0;"); }

__device__ __forceinline__ float blockReduceSum(float v, float* sh) {
    int lane = threadIdx.x & 31, w = threadIdx.x >> 5;
    #pragma unroll
    for (int o = 16; o; o >>= 1) v += __shfl_down_sync(0xffffffffu, v, o);
    if (lane == 0) sh[w] = v;
    __syncthreads();
    if (w == 0) {
        float r = (lane < (int)(blockDim.x >> 5)) ? sh[lane] : 0.f;
        #pragma unroll
        for (int o = 16; o; o >>= 1) r += __shfl_down_sync(0xffffffffu, r, o);
        if (lane == 0) sh[0] = r;
    }
    __syncthreads();
    float r = sh[0];
    __syncthreads();
    return r;
}

__device__ __forceinline__ float blockReduceMax(float v, float* sh) {
    int lane = threadIdx.x & 31, w = threadIdx.x >> 5;
    #pragma unroll
    for (int o = 16; o; o >>= 1) v = fmaxf(v, __shfl_down_sync(0xffffffffu, v, o));
    if (lane == 0) sh[w] = v;
    __syncthreads();
    if (w == 0) {
        float r = (lane < (int)(blockDim.x >> 5)) ? sh[lane] : -1e30f;
        #pragma unroll
        for (int o = 16; o; o >>= 1) r = fmaxf(r, __shfl_down_sync(0xffffffffu, r, o));
        if (lane == 0) sh[0] = r;
    }
    __syncthreads();
    float r = sh[0];
    __syncthreads();
    return r;
}

// GroupNorm: one block per (batch, group); fp32 in, bf16 out.
__global__ __launch_bounds__(256) void gn_kernel(const float* __restrict__ x,
                                                 const float* __restrict__ scale,
                                                 const float* __restrict__ bias) {
    __shared__ float sh[32];
    int b = blockIdx.x >> 5;
    int g = blockIdx.x & 31;
    const int VE = 16 * NSP / 4;   // 4096 float4
    const long base = ((long)b * CCH + (long)g * 16) * NSP;
    const float4* xp = (const float4*)(x + base);
    float s = 0.f, ss = 0.f;
    for (int i = threadIdx.x; i < VE; i += 256) {
        float4 t = xp[i];
        s  += t.x + t.y + t.z + t.w;
        ss += t.x * t.x + t.y * t.y + t.z * t.z + t.w * t.w;
    }
    s  = blockReduceSum(s, sh);
    ss = blockReduceSum(ss, sh);
    float mean = s * (1.f / 16384.f);
    float var  = ss * (1.f / 16384.f) - mean * mean;
    float rinv = rsqrtf(var + 1e-5f);
    uint2* hp = (uint2*)(g_h + base);
    for (int i = threadIdx.x; i < VE; i += 256) {
        int c = g * 16 + (i >> 8);
        float sc = scale[c] * rinv;
        float bi = bias[c] - mean * sc;
        float4 t = xp[i];
        uint2 o;
        o.x = pk(t.x * sc + bi, t.y * sc + bi);
        o.y = pk(t.z * sc + bi, t.w * sc + bi);
        hp[i] = o;
    }
}

// Convert the four 512x512 fp32 weights to bf16 (g_w16).
__global__ __launch_bounds__(256) void convw_kernel(const float* __restrict__ wq,
                                                    const float* __restrict__ wk,
                                                    const float* __restrict__ wv,
                                                    const float* __restrict__ wo) {
    const float* s = blockIdx.y == 0 ? wq : blockIdx.y == 1 ? wk : blockIdx.y == 2 ? wv : wo;
    bf16* d = g_w16 + (long)blockIdx.y * CCH * CCH;
    int iv = blockIdx.x * 256 + threadIdx.x;      // float4 index, 65536 total
    float4 v = ((const float4*)s)[iv];
    uint2 o;
    o.x = pk(v.x, v.y);
    o.y = pk(v.z, v.w);
    ((uint2*)d)[iv] = o;
}

// Row softmax over 1024 bf16, in place, single pass (row in registers).
__global__ __launch_bounds__(256) void softmax_kernel(bf16* __restrict__ attn) {
    __shared__ float sh[32];
    uint2* p = (uint2*)(attn + (long)blockIdx.x * NSP);
    uint2 raw = p[threadIdx.x];
    __nv_bfloat162 h0 = *(__nv_bfloat162*)&raw.x;
    __nv_bfloat162 h1 = *(__nv_bfloat162*)&raw.y;
    float a = __low2float(h0), b = __high2float(h0);
    float c = __low2float(h1), d = __high2float(h1);
    float m = fmaxf(fmaxf(a, b), fmaxf(c, d));
    m = blockReduceMax(m, sh);
    a = __expf(a - m); b = __expf(b - m); c = __expf(c - m); d = __expf(d - m);
    float s = a + b + c + d;
    s = blockReduceSum(s, sh);
    float inv = 1.f / s;
    raw.x = pk(a * inv, b * inv);
    raw.y = pk(c * inv, d * inv);
    p[threadIdx.x] = raw;
}

// Tensor-core batched GEMM, bf16 in / fp32 acc, cp.async double-buffered.
// C[b][i][j] = alpha * sum_k A[i*sAm + k*sAk] * B[k*sBk + j*sBn] (+bias[i]) (+res)
// AMODE 0: sAk==1 (k-fast)   AMODE 1: sAm==1 (m-fast)
// BMODE 0: sBn==1 (n-fast)   BMODE 1: sBk==1 (k-fast)
// CTA tile 128x256, 8 warps in 2(M) x 4(N), warp tile 64x64, acc 4x4 wmma frags.
template<int AMODE, int BMODE, bool HASB, bool HASR, bool F32O>
__global__ void __launch_bounds__(256) gemm_tc(
    const bf16* __restrict__ A, const bf16* __restrict__ B,
    const float* __restrict__ bias, const float* __restrict__ res,
    void* __restrict__ Cv, int Nn, int K,
    long sAm, long sAk, long sBk, long sBn,
    long batchA, long batchB, long batchC, float alpha)
{
    constexpr int AS_STR = (AMODE == 0) ? BK + PAD : BM + PAD;
    constexpr int A_TILE = (AMODE == 0) ? BM * AS_STR : BK * AS_STR;
    constexpr int BS_STR = (BMODE == 0) ? BN + PAD : BK + PAD;
    constexpr int B_TILE = (BMODE == 0) ? BK * BS_STR : BN * BS_STR;
    using AL = typename Sel<AMODE == 0, wmma::row_major, wmma::col_major>::type;
    using BL = typename Sel<BMODE == 0, wmma::row_major, wmma::col_major>::type;

    extern __shared__ __align__(16) bf16 sm[];
    bf16* As = sm;
    bf16* Bs = sm + 2 * A_TILE;

    const int bz = blockIdx.z;
    A += (long)bz * batchA;
    B += (long)bz * batchB;
    const int tid = threadIdx.x;
    const int warp = tid >> 5, lane = tid & 31;
    const int wn = warp & 3, wm = warp >> 2;     // warp tile 64(M) x 64(N)
    const int rowBase = blockIdx.y * BM;
    const int colBase = blockIdx.x * BN;

    wmma::fragment<wmma::accumulator, 16, 16, 16, float> acc[4][4];
    #pragma unroll
    for (int i = 0; i < 4; i++)
        #pragma unroll
        for (int j = 0; j < 4; j++) wmma::fill_fragment(acc[i][j], 0.f);

    auto stage = [&](int kt, int buf) {
        int k0 = kt * BK;
        // A: 4096 elems = 512 16B-chunks, 2 per thread
        #pragma unroll
        for (int t = 0; t < 2; t++) {
            int ci = tid + t * 256;
            const bf16* ga; bf16* sa;
            if (AMODE == 0) {
                int m = ci >> 2, kv = (ci & 3) * 8;
                ga = A + (long)(rowBase + m) * sAm + (k0 + kv);
                sa = As + buf * A_TILE + m * AS_STR + kv;
            } else {
                int kk = ci >> 4, mv = (ci & 15) * 8;
                ga = A + (rowBase + mv) + (long)(k0 + kk) * sAk;
                sa = As + buf * A_TILE + kk * AS_STR + mv;
            }
            cp16(sa, ga);
        }
        // B: 8192 elems = 1024 chunks, 4 per thread
        #pragma unroll
        for (int t = 0; t < 4; t++) {
            int ci = tid + t * 256;
            const bf16* gb; bf16* sb;
            if (BMODE == 0) {
                int kk = ci >> 5, nv = (ci & 31) * 8;
                gb = B + (long)(k0 + kk) * sBk + (colBase + nv);
                sb = Bs + buf * B_TILE + kk * BS_STR + nv;
            } else {
                int n = ci >> 2, kv = (ci & 3) * 8;
                gb = B + (long)(colBase + n) * sBn + (k0 + kv);
                sb = Bs + buf * B_TILE + n * BS_STR + kv;
            }
            cp16(sb, gb);
        }
        cp_commit();
    };

    const int KT = K >> 5;
    stage(0, 0);
    for (int kt = 0; kt < KT; kt++) {
        int buf = kt & 1;
        if (kt + 1 < KT) { stage(kt + 1, buf ^ 1); cp_wait1(); }
        else cp_wait0();
        __syncthreads();
        #pragma unroll
        for (int ks = 0; ks < BK; ks += 16) {
            wmma::fragment<wmma::matrix_a, 16, 16, 16, bf16, AL> af[4];
            #pragma unroll
            for (int i = 0; i < 4; i++) {
                const bf16* ap = (AMODE == 0)
                    ? As + buf * A_TILE + (wm * 64 + i * 16) * AS_STR + ks
                    : As + buf * A_TILE + ks * AS_STR + (wm * 64 + i * 16);
                wmma::load_matrix_sync(af[i], ap, AS_STR);
            }
            #pragma unroll
            for (int j = 0; j < 4; j++) {
                wmma::fragment<wmma::matrix_b, 16, 16, 16, bf16, BL> bfm;
                const bf16* bp = (BMODE == 0)
                    ? Bs + buf * B_TILE + ks * BS_STR + (wn * 64 + j * 16)
                    : Bs + buf * B_TILE + (wn * 64 + j * 16) * BS_STR + ks;
                wmma::load_matrix_sync(bfm, bp, BS_STR);
                #pragma unroll
                for (int i = 0; i < 4; i++)
                    wmma::mma_sync(acc[i][j], af[i], bfm, acc[i][j]);
            }
        }
        __syncthreads();
    }

    // Epilogue: per-warp smem bounce (aliases tile smem), fp32->bf16 16B stores.
    float* cw = (float*)sm + warp * (16 * 20);
    float* Cf = (float*)Cv;
    bf16*  Cb = (bf16*)Cv;
    const long cbatch = (long)bz * batchC;
    const int r  = lane >> 1;
    const int cb = (lane & 1) * 8;
    __syncthreads();
    #pragma unroll
    for (int i = 0; i < 4; i++) {
        #pragma unroll
        for (int j = 0; j < 4; j++) {
            #pragma unroll
            for (int t = 0; t < (int)acc[i][j].num_elements; t++)
                acc[i][j].x[t] *= alpha;
            wmma::store_matrix_sync(cw, acc[i][j], 20, wmma::mem_row_major);
            __syncwarp();
            float4 v0 = *(float4*)(cw + r * 20 + cb);
            float4 v1 = *(float4*)(cw + r * 20 + cb + 4);
            __syncwarp();
            int row = rowBase + wm * 64 + i * 16 + r;
            long coff = cbatch + (long)row * Nn + colBase + wn * 64 + j * 16 + cb;
            float ba = HASB ? bias[row] : 0.f;
            if (HASR) {
                const float4* rp = (const float4*)(res + coff);
                float4 r0 = rp[0], r1 = rp[1];
                v0.x += r0.x; v0.y += r0.y; v0.z += r0.z; v0.w += r0.w;
                v1.x += r1.x; v1.y += r1.y; v1.z += r1.z; v1.w += r1.w;
            }
            v0.x += ba; v0.y += ba; v0.z += ba; v0.w += ba;
            v1.x += ba; v1.y += ba; v1.z += ba; v1.w += ba;
            if (F32O) {
                *(float4*)(Cf + coff) = v0;
                *(float4*)(Cf + coff + 4) = v1;
            } else {
                uint4 u;
                u.x = pk(v0.x, v0.y); u.y = pk(v0.z, v0.w);
                u.z = pk(v1.x, v1.y); u.w = pk(v1.z, v1.w);
                *(uint4*)(Cb + coff) = u;
            }
        }
    }
}

#define GSM (80 * 1024)

extern "C" void kernel_launch(void* const* d_in, const int* in_sizes, int n_in,
                              void* d_out, int out_size) {
    const float* x  = (const float*)d_in[0];
    const float* gs = (const float*)d_in[1];
    const float* gb = (const float*)d_in[2];
    const float* wq = (const float*)d_in[3];
    const float* bq = (const float*)d_in[4];
    const float* wk = (const float*)d_in[5];
    const float* bk = (const float*)d_in[6];
    const float* wv = (const float*)d_in[7];
    const float* bv = (const float*)d_in[8];
    const float* wo = (const float*)d_in[9];
    const float* bo = (const float*)d_in[10];
    float* out = (float*)d_out;

    bf16 *h, *q, *k, *v, *attn, *hv, *w16;
    cudaGetSymbolAddress((void**)&h,    g_h);
    cudaGetSymbolAddress((void**)&q,    g_q);
    cudaGetSymbolAddress((void**)&k,    g_k);
    cudaGetSymbolAddress((void**)&v,    g_v);
    cudaGetSymbolAddress((void**)&attn, g_attn);
    cudaGetSymbolAddress((void**)&hv,   g_hv);
    cudaGetSymbolAddress((void**)&w16,  g_w16);

    const long CN = (long)CCH * NSP;   // 524288
    const long NN = (long)NSP * NSP;   // 1048576
    const long WW = (long)CCH * CCH;   // 262144
    const float scl = 1.0f / sqrtf((float)CCH);

    cudaFuncSetAttribute(gemm_tc<0,0,true,false,false>,
                         cudaFuncAttributeMaxDynamicSharedMemorySize, GSM);
    cudaFuncSetAttribute(gemm_tc<1,0,false,false,false>,
                         cudaFuncAttributeMaxDynamicSharedMemorySize, GSM);
    cudaFuncSetAttribute(gemm_tc<0,1,false,false,false>,
                         cudaFuncAttributeMaxDynamicSharedMemorySize, GSM);
    cudaFuncSetAttribute(gemm_tc<0,0,true,true,true>,
                         cudaFuncAttributeMaxDynamicSharedMemorySize, GSM);

    // 1) GroupNorm -> h (bf16); weights -> bf16
    gn_kernel<<<BSZ * NGROUPS, 256>>>(x, gs, gb);
    convw_kernel<<<dim3(WW / 4 / 256, 4), 256>>>(wq, wk, wv, wo);

    // 2) Q, K, V projections: w[512,512] @ h[512,1024] per batch (+bias)
    dim3 gProj(NSP / BN, CCH / BM, BSZ);
    gemm_tc<0,0,true,false,false><<<gProj, 256, GSM>>>(w16 + 0*WW, h, bq, nullptr, q,
        NSP, CCH, CCH, 1, NSP, 1, 0, CN, CN, 1.f);
    gemm_tc<0,0,true,false,false><<<gProj, 256, GSM>>>(w16 + 1*WW, h, bk, nullptr, k,
        NSP, CCH, CCH, 1, NSP, 1, 0, CN, CN, 1.f);
    gemm_tc<0,0,true,false,false><<<gProj, 256, GSM>>>(w16 + 2*WW, h, bv, nullptr, v,
        NSP, CCH, CCH, 1, NSP, 1, 0, CN, CN, 1.f);

    // 3) Scores: S[n,m] = scl * sum_c q[c,n] k[c,m]  (M=N=1024, K=512)
    dim3 gScore(NSP / BN, NSP / BM, BSZ);
    gemm_tc<1,0,false,false,false><<<gScore, 256, GSM>>>(q, k, nullptr, nullptr, attn,
        NSP, CCH, 1, NSP, NSP, 1, CN, CN, NN, scl);

    // 4) Row softmax (bf16 in/out)
    softmax_kernel<<<BSZ * NSP, 256>>>(attn);

    // 5) hv[c,n] = sum_m v[c,m] * attn[n,m]  (M=512, N=1024, K=1024)
    gemm_tc<0,1,false,false,false><<<gProj, 256, GSM>>>(v, attn, nullptr, nullptr, hv,
        NSP, NSP, NSP, 1, 1, NSP, CN, NN, CN, 1.f);

    // 6) out = wo @ hv + bo + x  (fp32 output)
    gemm_tc<0,0,true,true,true><<<gProj, 256, GSM>>>(w16 + 3*WW, hv, bo, x, out,
        NSP, CCH, CCH, 1, NSP, 1, 0, CN, CN, 1.f);
}

// round 11
// speedup vs baseline: 6.7392x; 1.1866x over previous
#include <cuda_runtime.h>
#include <cuda_bf16.h>
#include <mma.h>
#include <math.h>

using namespace nvcuda;
typedef __nv_bfloat16 bf16;

#define BSZ 16
#define CCH 512
#define NSP 1024
#define NGROUPS 32

#define BM 128
#define BN 128
#define BK 32
#define PAD 8
#define NTHR 128

// Scratch (device globals -- no allocation allowed).
__device__ __align__(16) bf16 g_h[(long)BSZ*CCH*NSP];
__device__ __align__(16) bf16 g_qkv[(long)BSZ*3*CCH*NSP];   // per batch: q[0:512) k[512:1024) v[1024:1536) rows x 1024
__device__ __align__(16) bf16 g_attn[(long)BSZ*NSP*NSP];
__device__ __align__(16) bf16 g_hv[(long)BSZ*CCH*NSP];
__device__ __align__(16) bf16 g_w16[4L*CCH*CCH];
__device__ float g_bqkv[3*CCH];

template<bool C, class T, class F> struct Sel { using type = T; };
template<class T, class F> struct Sel<false, T, F> { using type = F; };

__device__ __forceinline__ unsigned pk(float a, float b) {
    __nv_bfloat162 t = __floats2bfloat162_rn(a, b);
    return *(unsigned*)&t;
}

__device__ __forceinline__ void cp16(void* s, const void* g) {
    unsigned sa = (unsigned)__cvta_generic_to_shared(s);
    asm volatile("cp.async.cg.shared.global [%0], [%1], 16;" :: "r"(sa), "l"(g));
}
__device__ __forceinline__ void cp_commit() { asm volatile("cp.async.commit_group;"); }
__device__ __forceinline__ void cp_wait1() { asm volatile("cp.async.wait_group 1;"); }
__device__ __forceinline__ void cp_wait0() { asm volatile("cp.async.wait_group 0;"); }

__device__ __forceinline__ float blockReduceSum(float v, float* sh) {
    int lane = threadIdx.x & 31, w = threadIdx.x >> 5;
    #pragma unroll
    for (int o = 16; o; o >>= 1) v += __shfl_down_sync(0xffffffffu, v, o);
    if (lane == 0) sh[w] = v;
    __syncthreads();
    if (w == 0) {
        float r = (lane < (int)(blockDim.x >> 5)) ? sh[lane] : 0.f;
        #pragma unroll
        for (int o = 16; o; o >>= 1) r += __shfl_down_sync(0xffffffffu, r, o);
        if (lane == 0) sh[0] = r;
    }
    __syncthreads();
    float r = sh[0];
    __syncthreads();
    return r;
}

__device__ __forceinline__ float blockReduceMax(float v, float* sh) {
    int lane = threadIdx.x & 31, w = threadIdx.x >> 5;
    #pragma unroll
    for (int o = 16; o; o >>= 1) v = fmaxf(v, __shfl_down_sync(0xffffffffu, v, o));
    if (lane == 0) sh[w] = v;
    __syncthreads();
    if (w == 0) {
        float r = (lane < (int)(blockDim.x >> 5)) ? sh[lane] : -1e30f;
        #pragma unroll
        for (int o = 16; o; o >>= 1) r = fmaxf(r, __shfl_down_sync(0xffffffffu, r, o));
        if (lane == 0) sh[0] = r;
    }
    __syncthreads();
    float r = sh[0];
    __syncthreads();
    return r;
}

// GroupNorm: one block per (batch, group); fp32 in, bf16 out.
__global__ __launch_bounds__(256) void gn_kernel(const float* __restrict__ x,
                                                 const float* __restrict__ scale,
                                                 const float* __restrict__ bias) {
    __shared__ float sh[32];
    int b = blockIdx.x >> 5;
    int g = blockIdx.x & 31;
    const int VE = 16 * NSP / 4;   // 4096 float4
    const long base = ((long)b * CCH + (long)g * 16) * NSP;
    const float4* xp = (const float4*)(x + base);
    float s = 0.f, ss = 0.f;
    for (int i = threadIdx.x; i < VE; i += 256) {
        float4 t = xp[i];
        s  += t.x + t.y + t.z + t.w;
        ss += t.x * t.x + t.y * t.y + t.z * t.z + t.w * t.w;
    }
    s  = blockReduceSum(s, sh);
    ss = blockReduceSum(ss, sh);
    float mean = s * (1.f / 16384.f);
    float var  = ss * (1.f / 16384.f) - mean * mean;
    float rinv = rsqrtf(var + 1e-5f);
    uint2* hp = (uint2*)(g_h + base);
    for (int i = threadIdx.x; i < VE; i += 256) {
        int c = g * 16 + (i >> 8);
        float sc = scale[c] * rinv;
        float bi = bias[c] - mean * sc;
        float4 t = xp[i];
        uint2 o;
        o.x = pk(t.x * sc + bi, t.y * sc + bi);
        o.y = pk(t.z * sc + bi, t.w * sc + bi);
        hp[i] = o;
    }
}

// Convert the four 512x512 fp32 weights to bf16 (g_w16) and pack qkv biases.
__global__ __launch_bounds__(256) void convw_kernel(const float* __restrict__ wq,
                                                    const float* __restrict__ wk,
                                                    const float* __restrict__ wv,
                                                    const float* __restrict__ wo,
                                                    const float* __restrict__ bq,
                                                    const float* __restrict__ bk,
                                                    const float* __restrict__ bv) {
    const float* s = blockIdx.y == 0 ? wq : blockIdx.y == 1 ? wk : blockIdx.y == 2 ? wv : wo;
    bf16* d = g_w16 + (long)blockIdx.y * CCH * CCH;
    int iv = blockIdx.x * 256 + threadIdx.x;      // float4 index, 65536 total
    float4 v = ((const float4*)s)[iv];
    uint2 o;
    o.x = pk(v.x, v.y);
    o.y = pk(v.z, v.w);
    ((uint2*)d)[iv] = o;
    // pack biases (first 6 blocks of row 0 cover 1536 floats)
    if (blockIdx.y == 0 && blockIdx.x < 6) {
        int i = blockIdx.x * 256 + threadIdx.x;
        float bb = i < 512 ? bq[i] : (i < 1024 ? bk[i - 512] : bv[i - 1024]);
        g_bqkv[i] = bb;
    }
}

// Row softmax over 1024 bf16, in place, single pass (row in registers).
__global__ __launch_bounds__(256) void softmax_kernel(bf16* __restrict__ attn) {
    __shared__ float sh[32];
    uint2* p = (uint2*)(attn + (long)blockIdx.x * NSP);
    uint2 raw = p[threadIdx.x];
    __nv_bfloat162 h0 = *(__nv_bfloat162*)&raw.x;
    __nv_bfloat162 h1 = *(__nv_bfloat162*)&raw.y;
    float a = __low2float(h0), b = __high2float(h0);
    float c = __low2float(h1), d = __high2float(h1);
    float m = fmaxf(fmaxf(a, b), fmaxf(c, d));
    m = blockReduceMax(m, sh);
    a = __expf(a - m); b = __expf(b - m); c = __expf(c - m); d = __expf(d - m);
    float s = a + b + c + d;
    s = blockReduceSum(s, sh);
    float inv = 1.f / s;
    raw.x = pk(a * inv, b * inv);
    raw.y = pk(c * inv, d * inv);
    p[threadIdx.x] = raw;
}

// Tensor-core batched GEMM, bf16 in / fp32 acc, cp.async double-buffered.
// C[b][i][j] = alpha * sum_k A[i*sAm + k*sAk] * B[k*sBk + j*sBn] (+bias[i]) (+res)
// AMODE 0: sAk==1 (k-fast)   AMODE 1: sAm==1 (m-fast)
// BMODE 0: sBn==1 (n-fast)   BMODE 1: sBk==1 (k-fast)
// CTA tile 128x128, 4 warps in 2x2, warp tile 64x64, 3 CTAs/SM.
template<int AMODE, int BMODE, bool HASB, bool HASR, bool F32O>
__global__ void __launch_bounds__(NTHR, 3) gemm_tc(
    const bf16* __restrict__ A, const bf16* __restrict__ B,
    const float* __restrict__ bias, const float* __restrict__ res,
    void* __restrict__ Cv, int Nn, int K,
    long sAm, long sAk, long sBk, long sBn,
    long batchA, long batchB, long batchC, float alpha)
{
    constexpr int AS_STR = (AMODE == 0) ? BK + PAD : BM + PAD;
    constexpr int A_TILE = (AMODE == 0) ? BM * AS_STR : BK * AS_STR;
    constexpr int BS_STR = (BMODE == 0) ? BN + PAD : BK + PAD;
    constexpr int B_TILE = (BMODE == 0) ? BK * BS_STR : BN * BS_STR;
    using AL = typename Sel<AMODE == 0, wmma::row_major, wmma::col_major>::type;
    using BL = typename Sel<BMODE == 0, wmma::row_major, wmma::col_major>::type;

    extern __shared__ __align__(16) bf16 sm[];
    bf16* As = sm;
    bf16* Bs = sm + 2 * A_TILE;

    const int bz = blockIdx.z;
    A += (long)bz * batchA;
    B += (long)bz * batchB;
    const int tid = threadIdx.x;
    const int warp = tid >> 5, lane = tid & 31;
    const int wn = warp & 1, wm = warp >> 1;     // warp tile 64(M) x 64(N)
    const int rowBase = blockIdx.y * BM;
    const int colBase = blockIdx.x * BN;

    wmma::fragment<wmma::accumulator, 16, 16, 16, float> acc[4][4];
    #pragma unroll
    for (int i = 0; i < 4; i++)
        #pragma unroll
        for (int j = 0; j < 4; j++) wmma::fill_fragment(acc[i][j], 0.f);

    auto stage = [&](int kt, int buf) {
        int k0 = kt * BK;
        // A: 4096 elems = 512 16B-chunks, 4 per thread
        #pragma unroll
        for (int t = 0; t < 4; t++) {
            int ci = tid + t * NTHR;
            const bf16* ga; bf16* sa;
            if (AMODE == 0) {
                int m = ci >> 2, kv = (ci & 3) * 8;
                ga = A + (long)(rowBase + m) * sAm + (k0 + kv);
                sa = As + buf * A_TILE + m * AS_STR + kv;
            } else {
                int kk = ci >> 4, mv = (ci & 15) * 8;
                ga = A + (rowBase + mv) + (long)(k0 + kk) * sAk;
                sa = As + buf * A_TILE + kk * AS_STR + mv;
            }
            cp16(sa, ga);
        }
        // B: 4096 elems = 512 chunks, 4 per thread
        #pragma unroll
        for (int t = 0; t < 4; t++) {
            int ci = tid + t * NTHR;
            const bf16* gb; bf16* sb;
            if (BMODE == 0) {
                int kk = ci >> 4, nv = (ci & 15) * 8;
                gb = B + (long)(k0 + kk) * sBk + (colBase + nv);
                sb = Bs + buf * B_TILE + kk * BS_STR + nv;
            } else {
                int n = ci >> 2, kv = (ci & 3) * 8;
                gb = B + (long)(colBase + n) * sBn + (k0 + kv);
                sb = Bs + buf * B_TILE + n * BS_STR + kv;
            }
            cp16(sb, gb);
        }
        cp_commit();
    };

    const int KT = K >> 5;
    stage(0, 0);
    for (int kt = 0; kt < KT; kt++) {
        int buf = kt & 1;
        if (kt + 1 < KT) { stage(kt + 1, buf ^ 1); cp_wait1(); }
        else cp_wait0();
        __syncthreads();
        #pragma unroll
        for (int ks = 0; ks < BK; ks += 16) {
            wmma::fragment<wmma::matrix_a, 16, 16, 16, bf16, AL> af[4];
            #pragma unroll
            for (int i = 0; i < 4; i++) {
                const bf16* ap = (AMODE == 0)
                    ? As + buf * A_TILE + (wm * 64 + i * 16) * AS_STR + ks
                    : As + buf * A_TILE + ks * AS_STR + (wm * 64 + i * 16);
                wmma::load_matrix_sync(af[i], ap, AS_STR);
            }
            #pragma unroll
            for (int j = 0; j < 4; j++) {
                wmma::fragment<wmma::matrix_b, 16, 16, 16, bf16, BL> bfm;
                const bf16* bp = (BMODE == 0)
                    ? Bs + buf * B_TILE + ks * BS_STR + (wn * 64 + j * 16)
                    : Bs + buf * B_TILE + (wn * 64 + j * 16) * BS_STR + ks;
                wmma::load_matrix_sync(bfm, bp, BS_STR);
                #pragma unroll
                for (int i = 0; i < 4; i++)
                    wmma::mma_sync(acc[i][j], af[i], bfm, acc[i][j]);
            }
        }
        __syncthreads();
    }

    // Epilogue: per-warp smem bounce (aliases tile smem), fp32->bf16 16B stores.
    float* cw = (float*)sm + warp * (16 * 20);
    float* Cf = (float*)Cv;
    bf16*  Cb = (bf16*)Cv;
    const long cbatch = (long)bz * batchC;
    const int r  = lane >> 1;
    const int cb = (lane & 1) * 8;
    __syncthreads();
    #pragma unroll
    for (int i = 0; i < 4; i++) {
        #pragma unroll
        for (int j = 0; j < 4; j++) {
            #pragma unroll
            for (int t = 0; t < (int)acc[i][j].num_elements; t++)
                acc[i][j].x[t] *= alpha;
            wmma::store_matrix_sync(cw, acc[i][j], 20, wmma::mem_row_major);
            __syncwarp();
            float4 v0 = *(float4*)(cw + r * 20 + cb);
            float4 v1 = *(float4*)(cw + r * 20 + cb + 4);
            __syncwarp();
            int row = rowBase + wm * 64 + i * 16 + r;
            long coff = cbatch + (long)row * Nn + colBase + wn * 64 + j * 16 + cb;
            float ba = HASB ? bias[row] : 0.f;
            if (HASR) {
                const float4* rp = (const float4*)(res + coff);
                float4 r0 = rp[0], r1 = rp[1];
                v0.x += r0.x; v0.y += r0.y; v0.z += r0.z; v0.w += r0.w;
                v1.x += r1.x; v1.y += r1.y; v1.z += r1.z; v1.w += r1.w;
            }
            v0.x += ba; v0.y += ba; v0.z += ba; v0.w += ba;
            v1.x += ba; v1.y += ba; v1.z += ba; v1.w += ba;
            if (F32O) {
                *(float4*)(Cf + coff) = v0;
                *(float4*)(Cf + coff + 4) = v1;
            } else {
                uint4 u;
                u.x = pk(v0.x, v0.y); u.y = pk(v0.z, v0.w);
                u.z = pk(v1.x, v1.y); u.w = pk(v1.z, v1.w);
                *(uint4*)(Cb + coff) = u;
            }
        }
    }
}

#define GSM (42 * 1024)

extern "C" void kernel_launch(void* const* d_in, const int* in_sizes, int n_in,
                              void* d_out, int out_size) {
    const float* x  = (const float*)d_in[0];
    const float* gs = (const float*)d_in[1];
    const float* gb = (const float*)d_in[2];
    const float* wq = (const float*)d_in[3];
    const float* bq = (const float*)d_in[4];
    const float* wk = (const float*)d_in[5];
    const float* bk = (const float*)d_in[6];
    const float* wv = (const float*)d_in[7];
    const float* bv = (const float*)d_in[8];
    const float* wo = (const float*)d_in[9];
    const float* bo = (const float*)d_in[10];
    float* out = (float*)d_out;

    bf16 *h, *qkv, *attn, *hv, *w16;
    float* bqkv;
    cudaGetSymbolAddress((void**)&h,    g_h);
    cudaGetSymbolAddress((void**)&qkv,  g_qkv);
    cudaGetSymbolAddress((void**)&attn, g_attn);
    cudaGetSymbolAddress((void**)&hv,   g_hv);
    cudaGetSymbolAddress((void**)&w16,  g_w16);
    cudaGetSymbolAddress((void**)&bqkv, g_bqkv);

    const long CN  = (long)CCH * NSP;   // 524288
    const long NN  = (long)NSP * NSP;   // 1048576
    const long WW  = (long)CCH * CCH;   // 262144
    const long QKV = 3 * CN;
    const float scl = 1.0f / sqrtf((float)CCH);

    cudaFuncSetAttribute(gemm_tc<0,0,true,false,false>,
                         cudaFuncAttributeMaxDynamicSharedMemorySize, GSM);
    cudaFuncSetAttribute(gemm_tc<1,0,false,false,false>,
                         cudaFuncAttributeMaxDynamicSharedMemorySize, GSM);
    cudaFuncSetAttribute(gemm_tc<0,1,false,false,false>,
                         cudaFuncAttributeMaxDynamicSharedMemorySize, GSM);
    cudaFuncSetAttribute(gemm_tc<0,0,true,true,true>,
                         cudaFuncAttributeMaxDynamicSharedMemorySize, GSM);

    // 1) GroupNorm -> h (bf16); weights -> bf16 + bias pack
    gn_kernel<<<BSZ * NGROUPS, 256>>>(x, gs, gb);
    convw_kernel<<<dim3(WW / 4 / 256, 4), 256>>>(wq, wk, wv, wo, bq, bk, bv);

    // 2) Fused QKV projection: [1536,512] @ [512,1024] per batch (+bias)
    //    qkv[b] rows: 0..511 = q, 512..1023 = k, 1024..1535 = v
    dim3 gQKV(NSP / BN, 3 * CCH / BM, BSZ);
    gemm_tc<0,0,true,false,false><<<gQKV, NTHR, GSM>>>(w16, h, bqkv, nullptr, qkv,
        NSP, CCH, CCH, 1, NSP, 1, 0, CN, QKV, 1.f);

    // 3) Scores: S[n,m] = scl * sum_c q[c,n] k[c,m]  (M=N=1024, K=512)
    dim3 gScore(NSP / BN, NSP / BM, BSZ);
    gemm_tc<1,0,false,false,false><<<gScore, NTHR, GSM>>>(
        qkv, qkv + (long)CCH * NSP, nullptr, nullptr, attn,
        NSP, CCH, 1, NSP, NSP, 1, QKV, QKV, NN, scl);

    // 4) Row softmax (bf16 in/out)
    softmax_kernel<<<BSZ * NSP, 256>>>(attn);

    // 5) hv[c,n] = sum_m v[c,m] * attn[n,m]  (M=512, N=1024, K=1024)
    dim3 gProj(NSP / BN, CCH / BM, BSZ);
    gemm_tc<0,1,false,false,false><<<gProj, NTHR, GSM>>>(
        qkv + 2L * CCH * NSP, attn, nullptr, nullptr, hv,
        NSP, NSP, NSP, 1, 1, NSP, QKV, NN, CN, 1.f);

    // 6) out = wo @ hv + bo + x  (fp32 output)
    gemm_tc<0,0,true,true,true><<<gProj, NTHR, GSM>>>(w16 + 3*WW, hv, bo, x, out,
        NSP, CCH, CCH, 1, NSP, 1, 0, CN, CN, 1.f);
}

// round 13
// speedup vs baseline: 8.7610x; 1.3000x over previous
#include <cuda_runtime.h>
#include <cuda_fp16.h>
#include <mma.h>
#include <math.h>

using namespace nvcuda;
typedef __half f16;

#define BSZ 16
#define CCH 512
#define NSP 1024
#define NGROUPS 32

#define BM 128
#define BN 128
#define BK 32
#define PAD 8
#define NTHR 128

// Scratch (device globals -- no allocation allowed). All fp16.
__device__ __align__(16) f16 g_h[(long)BSZ*CCH*NSP];
__device__ __align__(16) f16 g_qkv[(long)BSZ*3*CCH*NSP];   // per batch: q|k|v, 1536 rows x 1024
__device__ __align__(16) f16 g_attn[(long)BSZ*NSP*NSP];
__device__ __align__(16) f16 g_hv[(long)BSZ*CCH*NSP];
__device__ __align__(16) f16 g_w16[4L*CCH*CCH];
__device__ float g_bqkv[3*CCH];

template<bool C, class T, class F> struct Sel { using type = T; };
template<class T, class F> struct Sel<false, T, F> { using type = F; };

__device__ __forceinline__ unsigned pkh(float a, float b) {
    __half2 t = __floats2half2_rn(a, b);
    return *(unsigned*)&t;
}

__device__ __forceinline__ void cp16(void* s, const void* g) {
    unsigned sa = (unsigned)__cvta_generic_to_shared(s);
    asm volatile("cp.async.cg.shared.global [%0], [%1], 16;" :: "r"(sa), "l"(g));
}
__device__ __forceinline__ void cp_commit() { asm volatile("cp.async.commit_group;"); }
__device__ __forceinline__ void cp_wait1() { asm volatile("cp.async.wait_group 1;"); }
__device__ __forceinline__ void cp_wait0() { asm volatile("cp.async.wait_group 0;"); }

__device__ __forceinline__ float blockReduceSum(float v, float* sh) {
    int lane = threadIdx.x & 31, w = threadIdx.x >> 5;
    #pragma unroll
    for (int o = 16; o; o >>= 1) v += __shfl_down_sync(0xffffffffu, v, o);
    if (lane == 0) sh[w] = v;
    __syncthreads();
    if (w == 0) {
        float r = (lane < (int)(blockDim.x >> 5)) ? sh[lane] : 0.f;
        #pragma unroll
        for (int o = 16; o; o >>= 1) r += __shfl_down_sync(0xffffffffu, r, o);
        if (lane == 0) sh[0] = r;
    }
    __syncthreads();
    float r = sh[0];
    __syncthreads();
    return r;
}

__device__ __forceinline__ float blockReduceMax(float v, float* sh) {
    int lane = threadIdx.x & 31, w = threadIdx.x >> 5;
    #pragma unroll
    for (int o = 16; o; o >>= 1) v = fmaxf(v, __shfl_down_sync(0xffffffffu, v, o));
    if (lane == 0) sh[w] = v;
    __syncthreads();
    if (w == 0) {
        float r = (lane < (int)(blockDim.x >> 5)) ? sh[lane] : -1e30f;
        #pragma unroll
        for (int o = 16; o; o >>= 1) r = fmaxf(r, __shfl_down_sync(0xffffffffu, r, o));
        if (lane == 0) sh[0] = r;
    }
    __syncthreads();
    float r = sh[0];
    __syncthreads();
    return r;
}

// GroupNorm: one block per (batch, group); fp32 in, fp16 out.
__global__ __launch_bounds__(256) void gn_kernel(const float* __restrict__ x,
                                                 const float* __restrict__ scale,
                                                 const float* __restrict__ bias) {
    __shared__ float sh[32];
    int b = blockIdx.x >> 5;
    int g = blockIdx.x & 31;
    const int VE = 16 * NSP / 4;   // 4096 float4
    const long base = ((long)b * CCH + (long)g * 16) * NSP;
    const float4* xp = (const float4*)(x + base);
    float s = 0.f, ss = 0.f;
    for (int i = threadIdx.x; i < VE; i += 256) {
        float4 t = xp[i];
        s  += t.x + t.y + t.z + t.w;
        ss += t.x * t.x + t.y * t.y + t.z * t.z + t.w * t.w;
    }
    s  = blockReduceSum(s, sh);
    ss = blockReduceSum(ss, sh);
    float mean = s * (1.f / 16384.f);
    float var  = ss * (1.f / 16384.f) - mean * mean;
    float rinv = rsqrtf(var + 1e-5f);
    uint2* hp = (uint2*)(g_h + base);
    for (int i = threadIdx.x; i < VE; i += 256) {
        int c = g * 16 + (i >> 8);
        float sc = scale[c] * rinv;
        float bi = bias[c] - mean * sc;
        float4 t = xp[i];
        uint2 o;
        o.x = pkh(t.x * sc + bi, t.y * sc + bi);
        o.y = pkh(t.z * sc + bi, t.w * sc + bi);
        hp[i] = o;
    }
}

// Convert the four 512x512 fp32 weights to fp16 (g_w16) and pack qkv biases.
__global__ __launch_bounds__(256) void convw_kernel(const float* __restrict__ wq,
                                                    const float* __restrict__ wk,
                                                    const float* __restrict__ wv,
                                                    const float* __restrict__ wo,
                                                    const float* __restrict__ bq,
                                                    const float* __restrict__ bk,
                                                    const float* __restrict__ bv) {
    const float* s = blockIdx.y == 0 ? wq : blockIdx.y == 1 ? wk : blockIdx.y == 2 ? wv : wo;
    f16* d = g_w16 + (long)blockIdx.y * CCH * CCH;
    int iv = blockIdx.x * 256 + threadIdx.x;      // float4 index, 65536 total
    float4 v = ((const float4*)s)[iv];
    uint2 o;
    o.x = pkh(v.x, v.y);
    o.y = pkh(v.z, v.w);
    ((uint2*)d)[iv] = o;
    if (blockIdx.y == 0 && blockIdx.x < 6) {
        int i = blockIdx.x * 256 + threadIdx.x;
        float bb = i < 512 ? bq[i] : (i < 1024 ? bk[i - 512] : bv[i - 1024]);
        g_bqkv[i] = bb;
    }
}

// Row softmax over 1024 fp16, in place, single pass (row in registers).
__global__ __launch_bounds__(256) void softmax_kernel(f16* __restrict__ attn) {
    __shared__ float sh[32];
    uint2* p = (uint2*)(attn + (long)blockIdx.x * NSP);
    uint2 raw = p[threadIdx.x];
    __half2 h0 = *(__half2*)&raw.x;
    __half2 h1 = *(__half2*)&raw.y;
    float a = __low2float(h0), b = __high2float(h0);
    float c = __low2float(h1), d = __high2float(h1);
    float m = fmaxf(fmaxf(a, b), fmaxf(c, d));
    m = blockReduceMax(m, sh);
    a = __expf(a - m); b = __expf(b - m); c = __expf(c - m); d = __expf(d - m);
    float s = a + b + c + d;
    s = blockReduceSum(s, sh);
    float inv = 1.f / s;
    raw.x = pkh(a * inv, b * inv);
    raw.y = pkh(c * inv, d * inv);
    p[threadIdx.x] = raw;
}

// Tensor-core batched GEMM, fp16 in / fp16 acc, cp.async double-buffered.
// C[b][i][j] = sum_k A[i*sAm + k*sAk] * B[k*sBk + j*sBn]   (+epilogue)
// AMODE 0: sAk==1 (k-fast)   AMODE 1: sAm==1 (m-fast)
// BMODE 0: sBn==1 (n-fast)   BMODE 1: sBk==1 (k-fast)
// EPI 0: direct fp16 fragment store
// EPI 1: fp16 out; v = acc*(row<scaleRows ? alpha : 1) + bias[row]
// EPI 2: fp32 out; v = acc + bias[row] + res[row*ldo+col]
// CTA tile 128x128, 4 warps in 2x2, warp tile 64x64, 4 CTAs/SM.
template<int AMODE, int BMODE, int EPI>
__global__ void __launch_bounds__(NTHR, 4) gemm_tc(
    const f16* __restrict__ A, const f16* __restrict__ B,
    const float* __restrict__ bias, const float* __restrict__ res,
    void* __restrict__ Cv, int Nn, int K,
    long sAm, long sAk, long sBk, long sBn,
    long batchA, long batchB, long batchC,
    float alpha, int scaleRows)
{
    constexpr int AS_STR = (AMODE == 0) ? BK + PAD : BM + PAD;
    constexpr int A_TILE = (AMODE == 0) ? BM * AS_STR : BK * AS_STR;
    constexpr int BS_STR = (BMODE == 0) ? BN + PAD : BK + PAD;
    constexpr int B_TILE = (BMODE == 0) ? BK * BS_STR : BN * BS_STR;
    using AL = typename Sel<AMODE == 0, wmma::row_major, wmma::col_major>::type;
    using BL = typename Sel<BMODE == 0, wmma::row_major, wmma::col_major>::type;

    extern __shared__ __align__(16) f16 sm[];
    f16* As = sm;
    f16* Bs = sm + 2 * A_TILE;

    const int bz = blockIdx.z;
    A += (long)bz * batchA;
    B += (long)bz * batchB;
    const int tid = threadIdx.x;
    const int warp = tid >> 5, lane = tid & 31;
    const int wn = warp & 1, wm = warp >> 1;     // warp tile 64(M) x 64(N)
    const int rowBase = blockIdx.y * BM;
    const int colBase = blockIdx.x * BN;

    wmma::fragment<wmma::accumulator, 16, 16, 16, f16> acc[4][4];
    #pragma unroll
    for (int i = 0; i < 4; i++)
        #pragma unroll
        for (int j = 0; j < 4; j++) wmma::fill_fragment(acc[i][j], __float2half(0.f));

    auto stage = [&](int kt, int buf) {
        int k0 = kt * BK;
        #pragma unroll
        for (int t = 0; t < 4; t++) {
            int ci = tid + t * NTHR;
            const f16* ga; f16* sa;
            if (AMODE == 0) {
                int m = ci >> 2, kv = (ci & 3) * 8;
                ga = A + (long)(rowBase + m) * sAm + (k0 + kv);
                sa = As + buf * A_TILE + m * AS_STR + kv;
            } else {
                int kk = ci >> 4, mv = (ci & 15) * 8;
                ga = A + (rowBase + mv) + (long)(k0 + kk) * sAk;
                sa = As + buf * A_TILE + kk * AS_STR + mv;
            }
            cp16(sa, ga);
        }
        #pragma unroll
        for (int t = 0; t < 4; t++) {
            int ci = tid + t * NTHR;
            const f16* gb; f16* sb;
            if (BMODE == 0) {
                int kk = ci >> 4, nv = (ci & 15) * 8;
                gb = B + (long)(k0 + kk) * sBk + (colBase + nv);
                sb = Bs + buf * B_TILE + kk * BS_STR + nv;
            } else {
                int n = ci >> 2, kv = (ci & 3) * 8;
                gb = B + (long)(colBase + n) * sBn + (k0 + kv);
                sb = Bs + buf * B_TILE + n * BS_STR + kv;
            }
            cp16(sb, gb);
        }
        cp_commit();
    };

    const int KT = K >> 5;
    stage(0, 0);
    for (int kt = 0; kt < KT; kt++) {
        int buf = kt & 1;
        if (kt + 1 < KT) { stage(kt + 1, buf ^ 1); cp_wait1(); }
        else cp_wait0();
        __syncthreads();
        #pragma unroll
        for (int ks = 0; ks < BK; ks += 16) {
            wmma::fragment<wmma::matrix_a, 16, 16, 16, f16, AL> af[4];
            #pragma unroll
            for (int i = 0; i < 4; i++) {
                const f16* ap = (AMODE == 0)
                    ? As + buf * A_TILE + (wm * 64 + i * 16) * AS_STR + ks
                    : As + buf * A_TILE + ks * AS_STR + (wm * 64 + i * 16);
                wmma::load_matrix_sync(af[i], ap, AS_STR);
            }
            #pragma unroll
            for (int j = 0; j < 4; j++) {
                wmma::fragment<wmma::matrix_b, 16, 16, 16, f16, BL> bfm;
                const f16* bp = (BMODE == 0)
                    ? Bs + buf * B_TILE + ks * BS_STR + (wn * 64 + j * 16)
                    : Bs + buf * B_TILE + (wn * 64 + j * 16) * BS_STR + ks;
                wmma::load_matrix_sync(bfm, bp, BS_STR);
                #pragma unroll
                for (int i = 0; i < 4; i++)
                    wmma::mma_sync(acc[i][j], af[i], bfm, acc[i][j]);
            }
        }
        __syncthreads();
    }

    const long cbatch = (long)bz * batchC;

    if (EPI == 0) {
        // Direct fp16 fragment stores to global.
        f16* Cb = (f16*)Cv + cbatch;
        #pragma unroll
        for (int i = 0; i < 4; i++) {
            #pragma unroll
            for (int j = 0; j < 4; j++) {
                f16* cp = Cb + (long)(rowBase + wm * 64 + i * 16) * Nn
                             + colBase + wn * 64 + j * 16;
                wmma::store_matrix_sync(cp, acc[i][j], Nn, wmma::mem_row_major);
            }
        }
        return;
    }

    // Bounce epilogue: fp16 frag -> smem -> processed stores.
    f16* cw = sm + warp * (16 * 24);
    const int r  = lane >> 1;
    const int cb = (lane & 1) * 8;
    #pragma unroll
    for (int i = 0; i < 4; i++) {
        #pragma unroll
        for (int j = 0; j < 4; j++) {
            wmma::store_matrix_sync(cw, acc[i][j], 24, wmma::mem_row_major);
            __syncwarp();
            uint2 raw = *(uint2*)(cw + r * 24 + cb);
            __syncwarp();
            __half2 p0 = *(__half2*)&raw.x;
            __half2 p1 = *(__half2*)&raw.y;
            float f0 = __low2float(p0), f1 = __high2float(p0);
            float f2 = __low2float(p1), f3 = __high2float(p1);
            uint2 raw2 = *(uint2*)(cw + r * 24 + cb + 4);
            __half2 p2 = *(__half2*)&raw2.x;
            __half2 p3 = *(__half2*)&raw2.y;
            float f4 = __low2float(p2), f5 = __high2float(p2);
            float f6 = __low2float(p3), f7 = __high2float(p3);
            int row = rowBase + wm * 64 + i * 16 + r;
            long coff = cbatch + (long)row * Nn + colBase + wn * 64 + j * 16 + cb;
            float ba = bias[row];
            if (EPI == 1) {
                float a = (row < scaleRows) ? alpha : 1.f;
                f0 = f0 * a + ba; f1 = f1 * a + ba; f2 = f2 * a + ba; f3 = f3 * a + ba;
                f4 = f4 * a + ba; f5 = f5 * a + ba; f6 = f6 * a + ba; f7 = f7 * a + ba;
                uint4 u;
                u.x = pkh(f0, f1); u.y = pkh(f2, f3);
                u.z = pkh(f4, f5); u.w = pkh(f6, f7);
                *(uint4*)((f16*)Cv + coff) = u;
            } else {
                const float4* rp = (const float4*)(res + coff);
                float4 r0 = rp[0], r1 = rp[1];
                float4 v0, v1;
                v0.x = f0 + ba + r0.x; v0.y = f1 + ba + r0.y;
                v0.z = f2 + ba + r0.z; v0.w = f3 + ba + r0.w;
                v1.x = f4 + ba + r1.x; v1.y = f5 + ba + r1.y;
                v1.z = f6 + ba + r1.z; v1.w = f7 + ba + r1.w;
                float* Cf = (float*)Cv;
                *(float4*)(Cf + coff) = v0;
                *(float4*)(Cf + coff + 4) = v1;
            }
        }
    }
}

#define GSM (42 * 1024)

extern "C" void kernel_launch(void* const* d_in, const int* in_sizes, int n_in,
                              void* d_out, int out_size) {
    const float* x  = (const float*)d_in[0];
    const float* gs = (const float*)d_in[1];
    const float* gb = (const float*)d_in[2];
    const float* wq = (const float*)d_in[3];
    const float* bq = (const float*)d_in[4];
    const float* wk = (const float*)d_in[5];
    const float* bk = (const float*)d_in[6];
    const float* wv = (const float*)d_in[7];
    const float* bv = (const float*)d_in[8];
    const float* wo = (const float*)d_in[9];
    const float* bo = (const float*)d_in[10];
    float* out = (float*)d_out;

    f16 *h, *qkv, *attn, *hv, *w16;
    float* bqkv;
    cudaGetSymbolAddress((void**)&h,    g_h);
    cudaGetSymbolAddress((void**)&qkv,  g_qkv);
    cudaGetSymbolAddress((void**)&attn, g_attn);
    cudaGetSymbolAddress((void**)&hv,   g_hv);
    cudaGetSymbolAddress((void**)&w16,  g_w16);
    cudaGetSymbolAddress((void**)&bqkv, g_bqkv);

    const long CN  = (long)CCH * NSP;   // 524288
    const long NN  = (long)NSP * NSP;   // 1048576
    const long WW  = (long)CCH * CCH;   // 262144
    const long QKV = 3 * CN;
    const float scl = 1.0f / sqrtf((float)CCH);

    cudaFuncSetAttribute(gemm_tc<0,0,1>, cudaFuncAttributeMaxDynamicSharedMemorySize, GSM);
    cudaFuncSetAttribute(gemm_tc<1,0,0>, cudaFuncAttributeMaxDynamicSharedMemorySize, GSM);
    cudaFuncSetAttribute(gemm_tc<0,1,0>, cudaFuncAttributeMaxDynamicSharedMemorySize, GSM);
    cudaFuncSetAttribute(gemm_tc<0,0,2>, cudaFuncAttributeMaxDynamicSharedMemorySize, GSM);

    // 1) GroupNorm -> h (fp16); weights -> fp16 + bias pack
    gn_kernel<<<BSZ * NGROUPS, 256>>>(x, gs, gb);
    convw_kernel<<<dim3(WW / 4 / 256, 4), 256>>>(wq, wk, wv, wo, bq, bk, bv);

    // 2) Fused QKV projection: [1536,512] @ [512,1024] per batch.
    //    q rows (0..511) get *scl folded in; bias added for all rows.
    dim3 gQKV(NSP / BN, 3 * CCH / BM, BSZ);
    gemm_tc<0,0,1><<<gQKV, NTHR, GSM>>>(w16, h, bqkv, nullptr, qkv,
        NSP, CCH, CCH, 1, NSP, 1, 0, CN, QKV, scl, CCH);

    // 3) Scores: S[n,m] = sum_c q[c,n] k[c,m]  (scl pre-folded into q)
    dim3 gScore(NSP / BN, NSP / BM, BSZ);
    gemm_tc<1,0,0><<<gScore, NTHR, GSM>>>(
        qkv, qkv + (long)CCH * NSP, nullptr, nullptr, attn,
        NSP, CCH, 1, NSP, NSP, 1, QKV, QKV, NN, 1.f, 0);

    // 4) Row softmax (fp16 in/out)
    softmax_kernel<<<BSZ * NSP, 256>>>(attn);

    // 5) hv[c,n] = sum_m v[c,m] * attn[n,m]  (M=512, N=1024, K=1024)
    dim3 gProj(NSP / BN, CCH / BM, BSZ);
    gemm_tc<0,1,0><<<gProj, NTHR, GSM>>>(
        qkv + 2L * CCH * NSP, attn, nullptr, nullptr, hv,
        NSP, NSP, NSP, 1, 1, NSP, QKV, NN, CN, 1.f, 0);

    // 6) out = wo @ hv + bo + x  (fp32 output)
    gemm_tc<0,0,2><<<gProj, NTHR, GSM>>>(w16 + 3*WW, hv, bo, x, out,
        NSP, CCH, CCH, 1, NSP, 1, 0, CN, CN, 1.f, 0);
}